// round 3
// baseline (speedup 1.0000x reference)
#include <cuda_runtime.h>

// Scratch for the per-row weighted spike sums (allocation-free rule).
#define MAX_M 50016
__device__ float d_Sg[MAX_M];
__device__ float d_Si[MAX_M];

// ---------------------------------------------------------------------------
// Kernel 1: per-row weighted sums over synapses.
//   Sg[i] = sum_j spikes[i,j] * |w[j]|
//   Si[i] = sum_j spikes[i,j] * (vrev[j]*|w[j]|)
// One warp per row, float4 loads, weights staged in shared memory.
// Streams the 100 MB spikes matrix exactly once (DRAM-bound, ~16-20 us).
// spikes are {0,1} so products are exact; only ~10 nonzero terms per row.
// ---------------------------------------------------------------------------
__global__ void rowdot_kernel(const float* __restrict__ spikes,
                              const float* __restrict__ w,
                              const float* __restrict__ vrev,
                              int m, int n) {
    __shared__ float4 s_aw[128];   // |w| packed as float4 (n <= 512)
    __shared__ float4 s_wv[128];   // vrev*|w| (elementwise rn mul, matches ref)

    const int tid  = threadIdx.x;
    const int lane = tid & 31;
    const int wrp  = tid >> 5;
    const int nv4  = n >> 2;       // n = 500 -> 125 float4 exactly

    for (int j = tid; j < nv4; j += blockDim.x) {
        float4 wj = reinterpret_cast<const float4*>(w)[j];
        float4 vj = reinterpret_cast<const float4*>(vrev)[j];
        float4 aw = make_float4(fabsf(wj.x), fabsf(wj.y), fabsf(wj.z), fabsf(wj.w));
        s_aw[j] = aw;
        s_wv[j] = make_float4(__fmul_rn(vj.x, aw.x), __fmul_rn(vj.y, aw.y),
                              __fmul_rn(vj.z, aw.z), __fmul_rn(vj.w, aw.w));
    }
    __syncthreads();

    const int row = blockIdx.x * (blockDim.x >> 5) + wrp;
    if (row >= m) return;

    const float4* rp = reinterpret_cast<const float4*>(spikes + (size_t)row * n);
    float accg = 0.0f, acci = 0.0f;
    for (int j = lane; j < nv4; j += 32) {
        float4 s  = rp[j];
        float4 aw = s_aw[j];
        float4 wv = s_wv[j];
        accg = fmaf(s.x, aw.x, accg); accg = fmaf(s.y, aw.y, accg);
        accg = fmaf(s.z, aw.z, accg); accg = fmaf(s.w, aw.w, accg);
        acci = fmaf(s.x, wv.x, acci); acci = fmaf(s.y, wv.y, acci);
        acci = fmaf(s.z, wv.z, acci); acci = fmaf(s.w, wv.w, acci);
    }
    for (int j = (nv4 << 2) + lane; j < n; j += 32) {  // tail (unused for n=500)
        float aw = fabsf(w[j]);
        float sv = spikes[(size_t)row * n + j];
        accg = fmaf(sv, aw, accg);
        acci = fmaf(sv, __fmul_rn(vrev[j], aw), acci);
    }

    #pragma unroll
    for (int o = 16; o > 0; o >>= 1) {
        accg += __shfl_down_sync(0xffffffffu, accg, o);
        acci += __shfl_down_sync(0xffffffffu, acci, o);
    }
    if (lane == 0) {
        d_Sg[row] = accg;
        d_Si[row] = acci;
    }
}

// ---------------------------------------------------------------------------
// Kernel 2: fused sequential recurrences on one warp (serial dependency due
// to the threshold reset).
//   G[0]=0, G[i] = (G[i-1] + Sg[i-1]) * decay   (add-then-mul, ref order)
//   I[0]=0, I[i] = (I[i-1] + Si[i-1]) * decay
//   a = 0.001*(1+G), b = 0.001*I  (computed in reference expression order)
//   vtr[i] = vtr[i-1] < 1 ? vtr[i-1]*(1-a[i-1]) + b[i-1] : 0   (NON-fused)
//
// decay = expf(-0.1f) computed in-kernel: same libdevice __nv_expf the
// XLA-GPU reference uses, so the constant matches bit-exactly.
// Lanes tile-load 32 (Sg,Si) coalesced (double-buffered), broadcast each
// step via shfl off the critical path; lane k snapshots step k's v so the
// 32 outputs store with one coalesced STG.
// ---------------------------------------------------------------------------
__global__ void scan_kernel(float* __restrict__ vtr, int m) {
    const float decay = expf(-0.1f);   // == __nv_expf(float(-1/10)), matches ref
    const float delta = 0.001f;
    const float gleak = 1.0f;
    const float theta = 1.0f;

    const int lane = threadIdx.x;
    if (lane == 0) vtr[0] = 0.0f;

    float G = 0.0f, I = 0.0f, v = 0.0f;

    // prefetch tile 0 (raw values; decay applied in-recurrence to match ref)
    float psg = (lane < m) ? d_Sg[lane] : 0.0f;
    float psi = (lane < m) ? d_Si[lane] : 0.0f;

    for (int t0 = 0; t0 < m - 1; t0 += 32) {
        float csg = psg, csi = psi;
        const int nb = t0 + 32;
        psg = (nb + lane < m) ? d_Sg[nb + lane] : 0.0f;
        psi = (nb + lane < m) ? d_Si[nb + lane] : 0.0f;

        const int steps = min(32, (m - 1) - t0);
        float vout = 0.0f;

        #pragma unroll
        for (int k = 0; k < 32; k++) {
            if (k >= steps) break;                       // uniform across warp
            const float sg = __shfl_sync(0xffffffffu, csg, k);
            const float si = __shfl_sync(0xffffffffu, csi, k);
            // a,b from G,I at index t0+k (== i-1 for output index i=t0+k+1),
            // in exact reference expression order, no FMA contraction:
            const float a = __fmul_rn(delta, __fadd_rn(gleak, G));
            const float b = __fmul_rn(delta, I);
            const float c = __fadd_rn(1.0f, -a);          // 1 - a
            const float u = __fadd_rn(__fmul_rn(v, c), b);
            v = (v < theta) ? u : 0.0f;                   // reset at threshold
            if (k == lane) vout = v;                      // snapshot for store
            // advance traces: (G + Sg) * decay, add-then-mul like the ref scan
            G = __fmul_rn(__fadd_rn(G, sg), decay);
            I = __fmul_rn(__fadd_rn(I, si), decay);
        }

        const int i = t0 + 1 + lane;
        if (lane < steps && i < m) vtr[i] = vout;
    }
}

// ---------------------------------------------------------------------------
extern "C" void kernel_launch(void* const* d_in, const int* in_sizes, int n_in,
                              void* d_out, int out_size) {
    const float* spikes = (const float*)d_in[0];
    const float* w      = (const float*)d_in[1];
    const float* vrev   = (const float*)d_in[2];
    float*       vtr    = (float*)d_out;

    const int n = in_sizes[1];               // 500
    const int m = in_sizes[0] / n;           // 50000

    const int rows_per_block = 8;            // 256 threads = 8 warps = 8 rows
    const int grid = (m + rows_per_block - 1) / rows_per_block;
    rowdot_kernel<<<grid, 256>>>(spikes, w, vrev, m, n);
    scan_kernel<<<1, 32>>>(vtr, m);
}

// round 5
// speedup vs baseline: 1.8811x; 1.8811x over previous
#include <cuda_runtime.h>

// Scratch for the per-row weighted spike sums (allocation-free rule).
// Padded to a TILE multiple past m; the pad region is never written by
// rowdot, so it stays at its zero static initialization (deterministic).
#define MAX_M 50432
__device__ float d_Sg[MAX_M];
__device__ float d_Si[MAX_M];

// ---------------------------------------------------------------------------
// Kernel 1: per-row weighted sums over synapses (unchanged — DRAM-bound,
// streams the 100 MB spikes matrix once).
//   Sg[i] = sum_j spikes[i,j] * |w[j]|
//   Si[i] = sum_j spikes[i,j] * (vrev[j]*|w[j]|)
// ---------------------------------------------------------------------------
__global__ void rowdot_kernel(const float* __restrict__ spikes,
                              const float* __restrict__ w,
                              const float* __restrict__ vrev,
                              int m, int n) {
    __shared__ float4 s_aw[128];
    __shared__ float4 s_wv[128];

    const int tid  = threadIdx.x;
    const int lane = tid & 31;
    const int wrp  = tid >> 5;
    const int nv4  = n >> 2;

    for (int j = tid; j < nv4; j += blockDim.x) {
        float4 wj = reinterpret_cast<const float4*>(w)[j];
        float4 vj = reinterpret_cast<const float4*>(vrev)[j];
        float4 aw = make_float4(fabsf(wj.x), fabsf(wj.y), fabsf(wj.z), fabsf(wj.w));
        s_aw[j] = aw;
        s_wv[j] = make_float4(__fmul_rn(vj.x, aw.x), __fmul_rn(vj.y, aw.y),
                              __fmul_rn(vj.z, aw.z), __fmul_rn(vj.w, aw.w));
    }
    __syncthreads();

    const int row = blockIdx.x * (blockDim.x >> 5) + wrp;
    if (row >= m) return;

    const float4* rp = reinterpret_cast<const float4*>(spikes + (size_t)row * n);
    float accg = 0.0f, acci = 0.0f;
    for (int j = lane; j < nv4; j += 32) {
        float4 s  = rp[j];
        float4 aw = s_aw[j];
        float4 wv = s_wv[j];
        accg = fmaf(s.x, aw.x, accg); accg = fmaf(s.y, aw.y, accg);
        accg = fmaf(s.z, aw.z, accg); accg = fmaf(s.w, aw.w, accg);
        acci = fmaf(s.x, wv.x, acci); acci = fmaf(s.y, wv.y, acci);
        acci = fmaf(s.z, wv.z, acci); acci = fmaf(s.w, wv.w, acci);
    }
    for (int j = (nv4 << 2) + lane; j < n; j += 32) {
        float aw = fabsf(w[j]);
        float sv = spikes[(size_t)row * n + j];
        accg = fmaf(sv, aw, accg);
        acci = fmaf(sv, __fmul_rn(vrev[j], aw), acci);
    }

    #pragma unroll
    for (int o = 16; o > 0; o >>= 1) {
        accg += __shfl_down_sync(0xffffffffu, accg, o);
        acci += __shfl_down_sync(0xffffffffu, acci, o);
    }
    if (lane == 0) {
        d_Sg[row] = accg;
        d_Si[row] = acci;
    }
}

// ---------------------------------------------------------------------------
// Kernel 2: three-warp pipelined serial scan. Each warp owns one dependency
// chain on its own SMSP (wid % 4):
//   warp0: G[i] = (G[i-1]+Sg[i-1])*decay ; emits c[i-1] = 1 - 0.001*(1+G[i-1])
//   warp1: I[i] = (I[i-1]+Si[i-1])*decay ; emits b[i-1] = 0.001*I[i-1]
//   warp2: v[i] = v[i-1] < 1 ? v[i-1]*c + b : 0   (consumes previous tile)
// Double-buffered smem (c,b) tiles of TILE steps, one __syncthreads per tile.
// All fp ops are in the exact reference rounding order (no contraction), so
// the v sequence is bit-identical to the round-2 passing kernel.
// decay = expf(-0.1f): same libdevice __nv_expf constant as the XLA ref.
// ---------------------------------------------------------------------------
#define TILE 256
#define TQ   (TILE / 32)

__global__ void scan3_kernel(float* __restrict__ vtr, int m) {
    __shared__ float s_c[2][TILE];
    __shared__ float s_b[2][TILE];

    const int   tid   = threadIdx.x;
    const int   wid   = tid >> 5;
    const int   lane  = tid & 31;
    const float decay = expf(-0.1f);

    const int nsteps = m - 1;                       // outputs 1..m-1
    const int ntiles = (nsteps + TILE - 1) / TILE;  // producers run ntiles

    if (tid == 0) vtr[0] = 0.0f;

    float G = 0.0f, I = 0.0f, v = 0.0f;

    for (int t = 0; t <= ntiles; ++t) {
        if (wid == 0) {
            if (t < ntiles) {
                const int base = t * TILE;          // pad zone reads are 0
                float sg[TQ];
                #pragma unroll
                for (int q = 0; q < TQ; ++q) sg[q] = d_Sg[base + q * 32 + lane];
                float* out = s_c[t & 1];
                #pragma unroll
                for (int k = 0; k < TILE; ++k) {
                    const float sgk = __shfl_sync(0xffffffffu, sg[k >> 5], k & 31);
                    const float a = __fmul_rn(0.001f, __fadd_rn(1.0f, G));
                    if (lane == 0) out[k] = __fadd_rn(1.0f, -a);   // c = 1 - a
                    G = __fmul_rn(__fadd_rn(G, sgk), decay);
                }
            }
        } else if (wid == 1) {
            if (t < ntiles) {
                const int base = t * TILE;
                float si[TQ];
                #pragma unroll
                for (int q = 0; q < TQ; ++q) si[q] = d_Si[base + q * 32 + lane];
                float* out = s_b[t & 1];
                #pragma unroll
                for (int k = 0; k < TILE; ++k) {
                    const float sik = __shfl_sync(0xffffffffu, si[k >> 5], k & 31);
                    if (lane == 0) out[k] = __fmul_rn(0.001f, I); // b = delta*I
                    I = __fmul_rn(__fadd_rn(I, sik), decay);
                }
            }
        } else {                                    // wid == 2: v chain
            if (t >= 1) {
                const int    base = (t - 1) * TILE;
                const float* cc   = s_c[(t - 1) & 1];
                const float* bb   = s_b[(t - 1) & 1];
                float vout[TQ];
                #pragma unroll
                for (int k = 0; k < TILE; ++k) {
                    const float c = cc[k];          // broadcast LDS
                    const float b = bb[k];
                    const float u = __fadd_rn(__fmul_rn(v, c), b);
                    v = (v < 1.0f) ? u : 0.0f;      // reset at threshold
                    if ((k & 31) == lane) vout[k >> 5] = v;
                }
                #pragma unroll
                for (int q = 0; q < TQ; ++q) {
                    const int i = base + 1 + q * 32 + lane;
                    if (i < m) vtr[i] = vout[q];
                }
            }
        }
        __syncthreads();                            // all 3 warps, every iter
    }
}

// ---------------------------------------------------------------------------
extern "C" void kernel_launch(void* const* d_in, const int* in_sizes, int n_in,
                              void* d_out, int out_size) {
    const float* spikes = (const float*)d_in[0];
    const float* w      = (const float*)d_in[1];
    const float* vrev   = (const float*)d_in[2];
    float*       vtr    = (float*)d_out;

    const int n = in_sizes[1];               // 500
    const int m = in_sizes[0] / n;           // 50000

    const int rows_per_block = 8;            // 256 threads = 8 warps = 8 rows
    const int grid = (m + rows_per_block - 1) / rows_per_block;
    rowdot_kernel<<<grid, 256>>>(spikes, w, vrev, m, n);
    scan3_kernel<<<1, 96>>>(vtr, m);
}